// round 1
// baseline (speedup 1.0000x reference)
#include <cuda_runtime.h>
#include <cuda_bf16.h>
#include <cfloat>

#define B_ 2
#define N_ 2048
#define C_ 1024
#define H_ 16
#define D_ 64

// Scratch (allocation-free rule: __device__ globals)
__device__ float g_q[B_ * H_ * N_ * D_];
__device__ float g_k[B_ * H_ * N_ * D_];
__device__ float g_v[B_ * H_ * N_ * D_];
__device__ float g_att[B_ * N_ * C_];

// ---------------------------------------------------------------------------
// Kernel 1: QKV GEMM  Y[4096,3072] = X[4096,1024] @ Wqkv[3072,1024]^T
// scattered into g_q/g_k/g_v with layout [B][H][N][d]
// ---------------------------------------------------------------------------
__global__ __launch_bounds__(256) void qkv_gemm_kernel(const float* __restrict__ X,
                                                       const float* __restrict__ W) {
    __shared__ float As[8][128];
    __shared__ float Bs[8][128];
    const int tid  = threadIdx.x;
    const int tcol = tid & 15, trow = tid >> 4;
    const int lrow = tid >> 1;
    const int lk   = (tid & 1) << 2;
    const float* Xp = X + (size_t)(blockIdx.y * 128 + lrow) * 1024 + lk;
    const float* Wp = W + (size_t)(blockIdx.x * 128 + lrow) * 1024 + lk;

    float acc[8][8];
#pragma unroll
    for (int u = 0; u < 8; u++)
#pragma unroll
        for (int v = 0; v < 8; v++) acc[u][v] = 0.f;

    for (int k0 = 0; k0 < 1024; k0 += 8) {
        float4 a4 = *(const float4*)(Xp + k0);
        float4 b4 = *(const float4*)(Wp + k0);
        As[lk + 0][lrow] = a4.x; As[lk + 1][lrow] = a4.y;
        As[lk + 2][lrow] = a4.z; As[lk + 3][lrow] = a4.w;
        Bs[lk + 0][lrow] = b4.x; Bs[lk + 1][lrow] = b4.y;
        Bs[lk + 2][lrow] = b4.z; Bs[lk + 3][lrow] = b4.w;
        __syncthreads();
#pragma unroll
        for (int kk = 0; kk < 8; kk++) {
            float4 a0 = *(const float4*)&As[kk][trow * 8];
            float4 a1 = *(const float4*)&As[kk][trow * 8 + 4];
            float4 b0 = *(const float4*)&Bs[kk][tcol * 8];
            float4 b1 = *(const float4*)&Bs[kk][tcol * 8 + 4];
            float ar[8] = {a0.x, a0.y, a0.z, a0.w, a1.x, a1.y, a1.z, a1.w};
            float br[8] = {b0.x, b0.y, b0.z, b0.w, b1.x, b1.y, b1.z, b1.w};
#pragma unroll
            for (int u = 0; u < 8; u++)
#pragma unroll
                for (int v = 0; v < 8; v++)
                    acc[u][v] = fmaf(ar[u], br[v], acc[u][v]);
        }
        __syncthreads();
    }

    const int m0 = blockIdx.y * 128 + trow * 8;
    const int n0 = blockIdx.x * 128 + tcol * 8;
#pragma unroll
    for (int u = 0; u < 8; u++) {
        int m = m0 + u;
        int b = m >> 11, nq = m & 2047;
#pragma unroll
        for (int v = 0; v < 8; v++) {
            int n = n0 + v;
            int s = n >> 10, r = n & 1023;
            int h = r >> 6, dd = r & 63;
            float* dst = (s == 0) ? g_q : (s == 1) ? g_k : g_v;
            dst[(((size_t)(b * H_ + h)) * N_ + nq) * D_ + dd] = acc[u][v];
        }
    }
}

// ---------------------------------------------------------------------------
// Kernel 2: LayerNorm over head_dim=64 for Q and K (one warp per row)
// ---------------------------------------------------------------------------
__global__ __launch_bounds__(256) void ln_kernel(const float* __restrict__ qg,
                                                 const float* __restrict__ qb,
                                                 const float* __restrict__ kg,
                                                 const float* __restrict__ kb) {
    int warp = blockIdx.x * 8 + (threadIdx.x >> 5);
    int lane = threadIdx.x & 31;
    if (warp >= B_ * H_ * N_) return;
    {
        float* row = g_q + (size_t)warp * 64;
        float x0 = row[lane], x1 = row[lane + 32];
        float sum = x0 + x1;
#pragma unroll
        for (int off = 16; off; off >>= 1) sum += __shfl_xor_sync(0xffffffffu, sum, off);
        float mu = sum * (1.0f / 64.0f);
        float d0 = x0 - mu, d1 = x1 - mu;
        float vs = d0 * d0 + d1 * d1;
#pragma unroll
        for (int off = 16; off; off >>= 1) vs += __shfl_xor_sync(0xffffffffu, vs, off);
        float rs = rsqrtf(vs * (1.0f / 64.0f) + 1e-5f);
        row[lane]      = d0 * rs * qg[lane]      + qb[lane];
        row[lane + 32] = d1 * rs * qg[lane + 32] + qb[lane + 32];
    }
    {
        float* row = g_k + (size_t)warp * 64;
        float x0 = row[lane], x1 = row[lane + 32];
        float sum = x0 + x1;
#pragma unroll
        for (int off = 16; off; off >>= 1) sum += __shfl_xor_sync(0xffffffffu, sum, off);
        float mu = sum * (1.0f / 64.0f);
        float d0 = x0 - mu, d1 = x1 - mu;
        float vs = d0 * d0 + d1 * d1;
#pragma unroll
        for (int off = 16; off; off >>= 1) vs += __shfl_xor_sync(0xffffffffu, vs, off);
        float rs = rsqrtf(vs * (1.0f / 64.0f) + 1e-5f);
        row[lane]      = d0 * rs * kg[lane]      + kb[lane];
        row[lane + 32] = d1 * rs * kg[lane + 32] + kb[lane + 32];
    }
}

// ---------------------------------------------------------------------------
// Kernel 3: flash-style attention. CTA = (q-tile of 64, head, batch).
// 128 threads as (tx 0..15, ty 0..7); each thread: 8x4 S-microtile, 8x4 O-microtile.
// ---------------------------------------------------------------------------
#define SMP 68   // shared pitch (floats): 4-aligned, conflict-benign

__global__ __launch_bounds__(128) void flash_kernel(const unsigned char* __restrict__ mask) {
    extern __shared__ float sm[];
    float(*Qst)[SMP] = (float(*)[SMP])(sm);                 // [dd][i] transposed
    float(*Kst)[SMP] = (float(*)[SMP])(sm + 64 * SMP);      // [dd][j] transposed
    float(*Vs)[SMP]  = (float(*)[SMP])(sm + 2 * 64 * SMP);  // [j][dd]
    float(*Ss)[SMP]  = (float(*)[SMP])(sm + 3 * 64 * SMP);  // [i][j]

    const int qt = blockIdx.x, h = blockIdx.y, b = blockIdx.z;
    const int tid = threadIdx.x;
    const int tx = tid & 15, ty = tid >> 4;
    const int lr = tid >> 1;
    const int lc = (tid & 1) * 32;
    const size_t headoff = ((size_t)(b * H_ + h)) * N_ * D_;

    // load Q tile, transposed
    {
        const float* qp = g_q + headoff + (size_t)(qt * 64 + lr) * 64 + lc;
#pragma unroll
        for (int i = 0; i < 32; i += 4) {
            float4 v = *(const float4*)(qp + i);
            Qst[lc + i + 0][lr] = v.x; Qst[lc + i + 1][lr] = v.y;
            Qst[lc + i + 2][lr] = v.z; Qst[lc + i + 3][lr] = v.w;
        }
    }

    float o[8][4];
    float m_i[8], l_i[8];
#pragma unroll
    for (int u = 0; u < 8; u++) {
        m_i[u] = -FLT_MAX; l_i[u] = 0.f;
#pragma unroll
        for (int c = 0; c < 4; c++) o[u][c] = 0.f;
    }

    const unsigned char* mrow = mask + (size_t)b * N_ * N_;
    const float scale = 0.125f;  // d^-0.5

    for (int kt = 0; kt < N_ / 64; kt++) {
        __syncthreads();  // previous PV done before overwriting K/V
        {
            const float* kp = g_k + headoff + (size_t)(kt * 64 + lr) * 64 + lc;
            const float* vp = g_v + headoff + (size_t)(kt * 64 + lr) * 64 + lc;
#pragma unroll
            for (int i = 0; i < 32; i += 4) {
                float4 kv = *(const float4*)(kp + i);
                Kst[lc + i + 0][lr] = kv.x; Kst[lc + i + 1][lr] = kv.y;
                Kst[lc + i + 2][lr] = kv.z; Kst[lc + i + 3][lr] = kv.w;
                float4 vv = *(const float4*)(vp + i);
                *(float4*)&Vs[lr][lc + i] = vv;
            }
        }
        __syncthreads();

        // S = Q @ K^T  (64x64x64)
        float s[8][4];
#pragma unroll
        for (int u = 0; u < 8; u++)
#pragma unroll
            for (int v = 0; v < 4; v++) s[u][v] = 0.f;

#pragma unroll 4
        for (int dd = 0; dd < 64; dd++) {
            float4 q0 = *(const float4*)&Qst[dd][ty * 8];
            float4 q1 = *(const float4*)&Qst[dd][ty * 8 + 4];
            float4 kf = *(const float4*)&Kst[dd][tx * 4];
            float qa[8] = {q0.x, q0.y, q0.z, q0.w, q1.x, q1.y, q1.z, q1.w};
            float ka[4] = {kf.x, kf.y, kf.z, kf.w};
#pragma unroll
            for (int u = 0; u < 8; u++)
#pragma unroll
                for (int v = 0; v < 4; v++)
                    s[u][v] = fmaf(qa[u], ka[v], s[u][v]);
        }

        // scale + mask + online softmax
#pragma unroll
        for (int u = 0; u < 8; u++) {
            int qrow = qt * 64 + ty * 8 + u;
            uchar4 mk = *(const uchar4*)(mrow + (size_t)qrow * N_ + kt * 64 + tx * 4);
            float sv[4];
            sv[0] = mk.x ? -FLT_MAX : s[u][0] * scale;
            sv[1] = mk.y ? -FLT_MAX : s[u][1] * scale;
            sv[2] = mk.z ? -FLT_MAX : s[u][2] * scale;
            sv[3] = mk.w ? -FLT_MAX : s[u][3] * scale;
            float mx = fmaxf(fmaxf(sv[0], sv[1]), fmaxf(sv[2], sv[3]));
#pragma unroll
            for (int off = 8; off; off >>= 1)
                mx = fmaxf(mx, __shfl_xor_sync(0xffffffffu, mx, off));
            float mnew = fmaxf(m_i[u], mx);
            float corr = __expf(m_i[u] - mnew);
            m_i[u] = mnew;
            float p0 = __expf(sv[0] - mnew);
            float p1 = __expf(sv[1] - mnew);
            float p2 = __expf(sv[2] - mnew);
            float p3 = __expf(sv[3] - mnew);
            *(float4*)&Ss[ty * 8 + u][tx * 4] = make_float4(p0, p1, p2, p3);
            float rsum = p0 + p1 + p2 + p3;
#pragma unroll
            for (int off = 8; off; off >>= 1)
                rsum += __shfl_xor_sync(0xffffffffu, rsum, off);
            l_i[u] = l_i[u] * corr + rsum;
#pragma unroll
            for (int c = 0; c < 4; c++) o[u][c] *= corr;
        }
        __syncthreads();

        // O += P @ V  (64x64x64)
#pragma unroll 4
        for (int j = 0; j < 64; j++) {
            float4 vf = *(const float4*)&Vs[j][tx * 4];
#pragma unroll
            for (int u = 0; u < 8; u++) {
                float pj = Ss[ty * 8 + u][j];
                o[u][0] = fmaf(pj, vf.x, o[u][0]);
                o[u][1] = fmaf(pj, vf.y, o[u][1]);
                o[u][2] = fmaf(pj, vf.z, o[u][2]);
                o[u][3] = fmaf(pj, vf.w, o[u][3]);
            }
        }
    }

    // epilogue: normalize and write [B,N,C] layout for proj GEMM
#pragma unroll
    for (int u = 0; u < 8; u++) {
        float inv = 1.0f / l_i[u];
        int nq = qt * 64 + ty * 8 + u;
        float4 r = make_float4(o[u][0] * inv, o[u][1] * inv, o[u][2] * inv, o[u][3] * inv);
        *(float4*)(g_att + ((size_t)(b * N_ + nq)) * C_ + h * 64 + tx * 4) = r;
    }
}

// ---------------------------------------------------------------------------
// Kernel 4: output projection  out[4096,1024] = g_att @ Wproj^T + b
// ---------------------------------------------------------------------------
__global__ __launch_bounds__(256) void proj_gemm_kernel(const float* __restrict__ W,
                                                        const float* __restrict__ bias,
                                                        float* __restrict__ out) {
    __shared__ float As[8][128];
    __shared__ float Bs[8][128];
    const int tid  = threadIdx.x;
    const int tcol = tid & 15, trow = tid >> 4;
    const int lrow = tid >> 1;
    const int lk   = (tid & 1) << 2;
    const float* Xp = g_att + (size_t)(blockIdx.y * 128 + lrow) * 1024 + lk;
    const float* Wp = W + (size_t)(blockIdx.x * 128 + lrow) * 1024 + lk;

    float acc[8][8];
#pragma unroll
    for (int u = 0; u < 8; u++)
#pragma unroll
        for (int v = 0; v < 8; v++) acc[u][v] = 0.f;

    for (int k0 = 0; k0 < 1024; k0 += 8) {
        float4 a4 = *(const float4*)(Xp + k0);
        float4 b4 = *(const float4*)(Wp + k0);
        As[lk + 0][lrow] = a4.x; As[lk + 1][lrow] = a4.y;
        As[lk + 2][lrow] = a4.z; As[lk + 3][lrow] = a4.w;
        Bs[lk + 0][lrow] = b4.x; Bs[lk + 1][lrow] = b4.y;
        Bs[lk + 2][lrow] = b4.z; Bs[lk + 3][lrow] = b4.w;
        __syncthreads();
#pragma unroll
        for (int kk = 0; kk < 8; kk++) {
            float4 a0 = *(const float4*)&As[kk][trow * 8];
            float4 a1 = *(const float4*)&As[kk][trow * 8 + 4];
            float4 b0 = *(const float4*)&Bs[kk][tcol * 8];
            float4 b1 = *(const float4*)&Bs[kk][tcol * 8 + 4];
            float ar[8] = {a0.x, a0.y, a0.z, a0.w, a1.x, a1.y, a1.z, a1.w};
            float br[8] = {b0.x, b0.y, b0.z, b0.w, b1.x, b1.y, b1.z, b1.w};
#pragma unroll
            for (int u = 0; u < 8; u++)
#pragma unroll
                for (int v = 0; v < 8; v++)
                    acc[u][v] = fmaf(ar[u], br[v], acc[u][v]);
        }
        __syncthreads();
    }

    const int m0 = blockIdx.y * 128 + trow * 8;
    const int n0 = blockIdx.x * 128 + tcol * 8;
#pragma unroll
    for (int u = 0; u < 8; u++) {
        int m = m0 + u;
#pragma unroll
        for (int v = 0; v < 8; v++) {
            int n = n0 + v;
            out[(size_t)m * 1024 + n] = acc[u][v] + bias[n];
        }
    }
}

// ---------------------------------------------------------------------------
extern "C" void kernel_launch(void* const* d_in, const int* in_sizes, int n_in,
                              void* d_out, int out_size) {
    const float*         x      = (const float*)d_in[0];
    const unsigned char* mask   = (const unsigned char*)d_in[1];
    const float*         w_qkv  = (const float*)d_in[2];
    const float*         w_proj = (const float*)d_in[3];
    const float*         b_proj = (const float*)d_in[4];
    const float*         qg     = (const float*)d_in[5];
    const float*         qb     = (const float*)d_in[6];
    const float*         kg     = (const float*)d_in[7];
    const float*         kb     = (const float*)d_in[8];
    float* out = (float*)d_out;

    // 1) QKV projection
    qkv_gemm_kernel<<<dim3(3 * C_ / 128, B_ * N_ / 128), 256>>>(x, w_qkv);

    // 2) Q/K LayerNorm (one warp per row; B*H*N rows)
    ln_kernel<<<(B_ * H_ * N_) / 8, 256>>>(qg, qb, kg, kb);

    // 3) attention
    const int smem = 4 * 64 * SMP * (int)sizeof(float);  // 69632 bytes
    cudaFuncSetAttribute(flash_kernel, cudaFuncAttributeMaxDynamicSharedMemorySize, smem);
    flash_kernel<<<dim3(N_ / 64, H_, B_), 128, smem>>>(mask);

    // 4) output projection + bias
    proj_gemm_kernel<<<dim3(C_ / 128, B_ * N_ / 128), 256>>>(w_proj, b_proj, out);
}

// round 4
// speedup vs baseline: 1.4557x; 1.4557x over previous
#include <cuda_runtime.h>
#include <cuda_bf16.h>
#include <cfloat>
#include <cstdint>

#define B_ 2
#define N_ 2048
#define C_ 1024
#define H_ 16
#define D_ 64

typedef __nv_bfloat16 bf16;

// ---------------------------------------------------------------------------
// Scratch (allocation-free rule: __device__ globals)
// ---------------------------------------------------------------------------
__device__ float g_q[B_ * H_ * N_ * D_];
__device__ float g_k[B_ * H_ * N_ * D_];
__device__ float g_v[B_ * H_ * N_ * D_];
__device__ bf16 g_xhi[B_ * N_ * C_], g_xlo[B_ * N_ * C_];
__device__ bf16 g_wqkvhi[3 * C_ * C_], g_wqkvlo[3 * C_ * C_];
__device__ bf16 g_wprojhi[C_ * C_], g_wprojlo[C_ * C_];
__device__ bf16 g_atthi[B_ * N_ * C_], g_attlo[B_ * N_ * C_];

// ---------------------------------------------------------------------------
// Family-agnostic PTX helpers (no tcgen05 — not available at .target sm_103)
// ---------------------------------------------------------------------------
__device__ __forceinline__ uint32_t smem_u32(const void* p) {
    uint32_t a;
    asm("{ .reg .u64 t; cvta.to.shared.u64 t, %1; cvt.u32.u64 %0, t; }" : "=r"(a) : "l"(p));
    return a;
}
#define CP16(saddr, gptr) \
    asm volatile("cp.async.cg.shared.global [%0], [%1], 16;" ::"r"(saddr), "l"(gptr) : "memory")
#define CP_COMMIT() asm volatile("cp.async.commit_group;" ::: "memory")
#define CP_WAIT0()  asm volatile("cp.async.wait_group 0;" ::: "memory")

__device__ __forceinline__ void mma_bf16(float c[4], uint32_t a0, uint32_t a1, uint32_t a2,
                                         uint32_t a3, uint32_t b0, uint32_t b1) {
    asm volatile(
        "mma.sync.aligned.m16n8k16.row.col.f32.bf16.bf16.f32 "
        "{%0,%1,%2,%3},{%4,%5,%6,%7},{%8,%9},{%0,%1,%2,%3};"
        : "+f"(c[0]), "+f"(c[1]), "+f"(c[2]), "+f"(c[3])
        : "r"(a0), "r"(a1), "r"(a2), "r"(a3), "r"(b0), "r"(b1));
}

// ---------------------------------------------------------------------------
// Shared 128x128x1024 split-bf16 (3-pass) mma.sync mainloop.
// 256 threads = 8 warps (2 x 4); warp tile 64x32; K-chunk 32, double buffered.
// SMEM (beyond 1KB header): 4 arrays x 2 bufs x 128 rows x 40 halves (pitch 40
// => conflict-free 32-bit LDS fragment loads).
// ---------------------------------------------------------------------------
#define PITCH 40
#define CH (128 * PITCH)      // halves per array-buffer
#define CHB (CH * 2)          // bytes per array-buffer
#define SMEM_GEMM (1024 + 8 * CHB)

__device__ __forceinline__ void gemm_ml(float acc[4][4][4],
                                        const bf16* __restrict__ Ahi,
                                        const bf16* __restrict__ Alo,
                                        const bf16* __restrict__ Bhi,
                                        const bf16* __restrict__ Blo,
                                        int m0, int n0, bf16* sa) {
    const int tid = threadIdx.x;
    const int wid = tid >> 5, lane = tid & 31;
    const int wm = wid & 1, wn = wid >> 1;
    const int r = lane >> 2, c4 = lane & 3;
    const int grow = tid >> 1, gcol = (tid & 1) * 16;

    const uint32_t sab = smem_u32(sa);
    const uint32_t so = (uint32_t)(grow * PITCH + gcol) * 2;  // bytes

    const bf16* pAh = Ahi + (size_t)(m0 + grow) * C_ + gcol;
    const bf16* pAl = Alo + (size_t)(m0 + grow) * C_ + gcol;
    const bf16* pBh = Bhi + (size_t)(n0 + grow) * C_ + gcol;
    const bf16* pBl = Blo + (size_t)(n0 + grow) * C_ + gcol;

    // prefetch chunk 0 into buffer 0
    {
        CP16(sab + 0 * CHB + so,      pAh);
        CP16(sab + 0 * CHB + so + 16, pAh + 8);
        CP16(sab + 2 * CHB + so,      pAl);
        CP16(sab + 2 * CHB + so + 16, pAl + 8);
        CP16(sab + 4 * CHB + so,      pBh);
        CP16(sab + 4 * CHB + so + 16, pBh + 8);
        CP16(sab + 6 * CHB + so,      pBl);
        CP16(sab + 6 * CHB + so + 16, pBl + 8);
        CP_COMMIT();
        CP_WAIT0();
    }
    __syncthreads();

    for (int c = 0; c < 32; c++) {
        if (c < 31) {  // issue async loads for next chunk into other buffer
            const int k0 = (c + 1) * 32;
            const uint32_t nb = (uint32_t)((c + 1) & 1) * CHB;
            CP16(sab + 0 * CHB + nb + so,      pAh + k0);
            CP16(sab + 0 * CHB + nb + so + 16, pAh + k0 + 8);
            CP16(sab + 2 * CHB + nb + so,      pAl + k0);
            CP16(sab + 2 * CHB + nb + so + 16, pAl + k0 + 8);
            CP16(sab + 4 * CHB + nb + so,      pBh + k0);
            CP16(sab + 4 * CHB + nb + so + 16, pBh + k0 + 8);
            CP16(sab + 6 * CHB + nb + so,      pBl + k0);
            CP16(sab + 6 * CHB + nb + so + 16, pBl + k0 + 8);
            CP_COMMIT();
        }
        // compute on current buffer
        const int bo = (c & 1) * CH;
        const bf16* ah = sa + bo;
        const bf16* al = sa + 2 * CH + bo;
        const bf16* bh = sa + 4 * CH + bo;
        const bf16* bl = sa + 6 * CH + bo;
#pragma unroll
        for (int kf = 0; kf < 2; kf++) {
            const int kb = kf * 16 + c4 * 2;
            uint32_t afh[4][4], afl[4][4];
#pragma unroll
            for (int mf = 0; mf < 4; mf++) {
                const int row = wm * 64 + mf * 16 + r;
                afh[mf][0] = *(const uint32_t*)(ah + row * PITCH + kb);
                afh[mf][1] = *(const uint32_t*)(ah + (row + 8) * PITCH + kb);
                afh[mf][2] = *(const uint32_t*)(ah + row * PITCH + kb + 8);
                afh[mf][3] = *(const uint32_t*)(ah + (row + 8) * PITCH + kb + 8);
                afl[mf][0] = *(const uint32_t*)(al + row * PITCH + kb);
                afl[mf][1] = *(const uint32_t*)(al + (row + 8) * PITCH + kb);
                afl[mf][2] = *(const uint32_t*)(al + row * PITCH + kb + 8);
                afl[mf][3] = *(const uint32_t*)(al + (row + 8) * PITCH + kb + 8);
            }
            uint32_t bfh[4][2], bfl[4][2];
#pragma unroll
            for (int nf = 0; nf < 4; nf++) {
                const int nn = wn * 32 + nf * 8 + r;
                bfh[nf][0] = *(const uint32_t*)(bh + nn * PITCH + kb);
                bfh[nf][1] = *(const uint32_t*)(bh + nn * PITCH + kb + 8);
                bfl[nf][0] = *(const uint32_t*)(bl + nn * PITCH + kb);
                bfl[nf][1] = *(const uint32_t*)(bl + nn * PITCH + kb + 8);
            }
#pragma unroll
            for (int mf = 0; mf < 4; mf++)
#pragma unroll
                for (int nf = 0; nf < 4; nf++) {
                    mma_bf16(acc[mf][nf], afh[mf][0], afh[mf][1], afh[mf][2], afh[mf][3],
                             bfh[nf][0], bfh[nf][1]);
                    mma_bf16(acc[mf][nf], afh[mf][0], afh[mf][1], afh[mf][2], afh[mf][3],
                             bfl[nf][0], bfl[nf][1]);
                    mma_bf16(acc[mf][nf], afl[mf][0], afl[mf][1], afl[mf][2], afl[mf][3],
                             bfh[nf][0], bfh[nf][1]);
                }
        }
        if (c < 31) CP_WAIT0();
        __syncthreads();
    }
}

// ---------------------------------------------------------------------------
// Kernel: fp32 -> (hi, lo) bf16 split. sel picks destination globals.
// ---------------------------------------------------------------------------
__global__ __launch_bounds__(256) void conv_kernel(const float* __restrict__ src,
                                                   int sel, int n4) {
    bf16* hi = (sel == 0) ? g_xhi : (sel == 1) ? g_wqkvhi : g_wprojhi;
    bf16* lo = (sel == 0) ? g_xlo : (sel == 1) ? g_wqkvlo : g_wprojlo;
    int i = blockIdx.x * 256 + threadIdx.x;
    if (i >= n4) return;
    float4 v = ((const float4*)src)[i];
    float a[4] = {v.x, v.y, v.z, v.w};
    bf16 h[4], l[4];
#pragma unroll
    for (int j = 0; j < 4; j++) {
        h[j] = __float2bfloat16_rn(a[j]);
        l[j] = __float2bfloat16_rn(a[j] - __bfloat162float(h[j]));
    }
    __nv_bfloat162 h01, h23, l01, l23;
    h01.x = h[0]; h01.y = h[1]; h23.x = h[2]; h23.y = h[3];
    l01.x = l[0]; l01.y = l[1]; l23.x = l[2]; l23.y = l[3];
    *(__nv_bfloat162*)(hi + 4 * (size_t)i)     = h01;
    *(__nv_bfloat162*)(hi + 4 * (size_t)i + 2) = h23;
    *(__nv_bfloat162*)(lo + 4 * (size_t)i)     = l01;
    *(__nv_bfloat162*)(lo + 4 * (size_t)i + 2) = l23;
}

// ---------------------------------------------------------------------------
// QKV GEMM (mma.sync split-bf16) + fused per-head LayerNorm + scatter.
// grid (24 n-tiles, 32 m-tiles), 256 threads.
// ---------------------------------------------------------------------------
#define DPITCH 132

__global__ __launch_bounds__(256) void qkv_mma_kernel(const float* __restrict__ qg,
                                                      const float* __restrict__ qb,
                                                      const float* __restrict__ kg,
                                                      const float* __restrict__ kb) {
    extern __shared__ char smc[];
    float* sgam = (float*)smc;
    float* sbet = (float*)(smc + 256);
    bf16* sa = (bf16*)(smc + 1024);

    const int n0 = blockIdx.x * 128, m0 = blockIdx.y * 128;
    const int s = n0 >> 10;  // 0=q 1=k 2=v
    if (threadIdx.x < 64 && s < 2) {
        const float* gg = (s == 0) ? qg : kg;
        const float* bb = (s == 0) ? qb : kb;
        sgam[threadIdx.x] = gg[threadIdx.x];
        sbet[threadIdx.x] = bb[threadIdx.x];
    }

    float acc[4][4][4];
#pragma unroll
    for (int a = 0; a < 4; a++)
#pragma unroll
        for (int b = 0; b < 4; b++)
#pragma unroll
            for (int cc = 0; cc < 4; cc++) acc[a][b][cc] = 0.f;

    gemm_ml(acc, g_xhi, g_xlo, g_wqkvhi, g_wqkvlo, m0, n0, sa);

    // stage accumulators to SMEM (reuses gemm buffers)
    float* Dst = (float*)(smc + 1024);
    const int wid = threadIdx.x >> 5, lane = threadIdx.x & 31;
    const int wm = wid & 1, wn = wid >> 1;
    const int r = lane >> 2, c4 = lane & 3;
#pragma unroll
    for (int mf = 0; mf < 4; mf++)
#pragma unroll
        for (int nf = 0; nf < 4; nf++) {
            const int m = wm * 64 + mf * 16 + r;
            const int n = wn * 32 + nf * 8 + c4 * 2;
            *(float2*)&Dst[m * DPITCH + n]       = make_float2(acc[mf][nf][0], acc[mf][nf][1]);
            *(float2*)&Dst[(m + 8) * DPITCH + n] = make_float2(acc[mf][nf][2], acc[mf][nf][3]);
        }
    __syncthreads();

    // per-(row, head) LayerNorm + scatter
    const int m = threadIdx.x >> 1, hc = threadIdx.x & 1;
    const float* rowp = Dst + m * DPITCH + hc * 64;
    float f[64];
#pragma unroll
    for (int i = 0; i < 64; i++) f[i] = rowp[i];
    if (s < 2) {
        float sum = 0.f;
#pragma unroll
        for (int i = 0; i < 64; i++) sum += f[i];
        float mu = sum * (1.0f / 64.0f);
        float vs = 0.f;
#pragma unroll
        for (int i = 0; i < 64; i++) { float d = f[i] - mu; vs += d * d; }
        float rs = rsqrtf(vs * (1.0f / 64.0f) + 1e-5f);
#pragma unroll
        for (int i = 0; i < 64; i++) f[i] = (f[i] - mu) * rs * sgam[i] + sbet[i];
    }
    const int bidx = m0 >> 11, nq = (m0 & 2047) + m;
    const int h = ((n0 & 1023) >> 6) + hc;
    float* dstb = (s == 0) ? g_q : (s == 1) ? g_k : g_v;
    const size_t base = (((size_t)(bidx * H_ + h)) * N_ + nq) * D_;
#pragma unroll
    for (int i = 0; i < 64; i += 4)
        *(float4*)&dstb[base + i] = make_float4(f[i], f[i + 1], f[i + 2], f[i + 3]);
}

// ---------------------------------------------------------------------------
// Projection GEMM (mma.sync split-bf16) + bias. grid (8, 32), 256 threads.
// ---------------------------------------------------------------------------
__global__ __launch_bounds__(256) void proj_mma_kernel(const float* __restrict__ bias,
                                                       float* __restrict__ out) {
    extern __shared__ char smc[];
    float* sbias = (float*)smc;
    bf16* sa = (bf16*)(smc + 1024);
    const int n0 = blockIdx.x * 128, m0 = blockIdx.y * 128;
    if (threadIdx.x < 128) sbias[threadIdx.x] = bias[n0 + threadIdx.x];

    float acc[4][4][4];
#pragma unroll
    for (int a = 0; a < 4; a++)
#pragma unroll
        for (int b = 0; b < 4; b++)
#pragma unroll
            for (int cc = 0; cc < 4; cc++) acc[a][b][cc] = 0.f;

    gemm_ml(acc, g_atthi, g_attlo, g_wprojhi, g_wprojlo, m0, n0, sa);

    const int wid = threadIdx.x >> 5, lane = threadIdx.x & 31;
    const int wm = wid & 1, wn = wid >> 1;
    const int r = lane >> 2, c4 = lane & 3;
#pragma unroll
    for (int mf = 0; mf < 4; mf++)
#pragma unroll
        for (int nf = 0; nf < 4; nf++) {
            const int m = wm * 64 + mf * 16 + r;
            const int n = wn * 32 + nf * 8 + c4 * 2;
            const float b0 = sbias[n], b1 = sbias[n + 1];
            *(float2*)&out[(size_t)(m0 + m) * C_ + n0 + n] =
                make_float2(acc[mf][nf][0] + b0, acc[mf][nf][1] + b1);
            *(float2*)&out[(size_t)(m0 + m + 8) * C_ + n0 + n] =
                make_float2(acc[mf][nf][2] + b0, acc[mf][nf][3] + b1);
        }
}

// ---------------------------------------------------------------------------
// Flash attention (fp32 SIMT) — epilogue writes split-bf16 for proj GEMM.
// ---------------------------------------------------------------------------
#define SMP 68

__global__ __launch_bounds__(128) void flash_kernel(const unsigned char* __restrict__ mask) {
    extern __shared__ float smf[];
    float(*Qst)[SMP] = (float(*)[SMP])(smf);
    float(*Kst)[SMP] = (float(*)[SMP])(smf + 64 * SMP);
    float(*Vs)[SMP]  = (float(*)[SMP])(smf + 2 * 64 * SMP);
    float(*Ss)[SMP]  = (float(*)[SMP])(smf + 3 * 64 * SMP);

    const int qt = blockIdx.x, h = blockIdx.y, b = blockIdx.z;
    const int tid = threadIdx.x;
    const int tx = tid & 15, ty = tid >> 4;
    const int lr = tid >> 1;
    const int lc = (tid & 1) * 32;
    const size_t headoff = ((size_t)(b * H_ + h)) * N_ * D_;

    {
        const float* qp = g_q + headoff + (size_t)(qt * 64 + lr) * 64 + lc;
#pragma unroll
        for (int i = 0; i < 32; i += 4) {
            float4 v = *(const float4*)(qp + i);
            Qst[lc + i + 0][lr] = v.x; Qst[lc + i + 1][lr] = v.y;
            Qst[lc + i + 2][lr] = v.z; Qst[lc + i + 3][lr] = v.w;
        }
    }

    float o[8][4];
    float m_i[8], l_i[8];
#pragma unroll
    for (int u = 0; u < 8; u++) {
        m_i[u] = -FLT_MAX; l_i[u] = 0.f;
#pragma unroll
        for (int c = 0; c < 4; c++) o[u][c] = 0.f;
    }

    const unsigned char* mrow = mask + (size_t)b * N_ * N_;
    const float scale = 0.125f;

    for (int kt = 0; kt < N_ / 64; kt++) {
        __syncthreads();
        {
            const float* kp = g_k + headoff + (size_t)(kt * 64 + lr) * 64 + lc;
            const float* vp = g_v + headoff + (size_t)(kt * 64 + lr) * 64 + lc;
#pragma unroll
            for (int i = 0; i < 32; i += 4) {
                float4 kv = *(const float4*)(kp + i);
                Kst[lc + i + 0][lr] = kv.x; Kst[lc + i + 1][lr] = kv.y;
                Kst[lc + i + 2][lr] = kv.z; Kst[lc + i + 3][lr] = kv.w;
                float4 vv = *(const float4*)(vp + i);
                *(float4*)&Vs[lr][lc + i] = vv;
            }
        }
        __syncthreads();

        float s[8][4];
#pragma unroll
        for (int u = 0; u < 8; u++)
#pragma unroll
            for (int v = 0; v < 4; v++) s[u][v] = 0.f;

#pragma unroll 4
        for (int dd = 0; dd < 64; dd++) {
            float4 q0 = *(const float4*)&Qst[dd][ty * 8];
            float4 q1 = *(const float4*)&Qst[dd][ty * 8 + 4];
            float4 kf = *(const float4*)&Kst[dd][tx * 4];
            float qa[8] = {q0.x, q0.y, q0.z, q0.w, q1.x, q1.y, q1.z, q1.w};
            float ka[4] = {kf.x, kf.y, kf.z, kf.w};
#pragma unroll
            for (int u = 0; u < 8; u++)
#pragma unroll
                for (int v = 0; v < 4; v++)
                    s[u][v] = fmaf(qa[u], ka[v], s[u][v]);
        }

#pragma unroll
        for (int u = 0; u < 8; u++) {
            int qrow = qt * 64 + ty * 8 + u;
            uchar4 mk = *(const uchar4*)(mrow + (size_t)qrow * N_ + kt * 64 + tx * 4);
            float sv[4];
            sv[0] = mk.x ? -FLT_MAX : s[u][0] * scale;
            sv[1] = mk.y ? -FLT_MAX : s[u][1] * scale;
            sv[2] = mk.z ? -FLT_MAX : s[u][2] * scale;
            sv[3] = mk.w ? -FLT_MAX : s[u][3] * scale;
            float mx = fmaxf(fmaxf(sv[0], sv[1]), fmaxf(sv[2], sv[3]));
#pragma unroll
            for (int off = 8; off; off >>= 1)
                mx = fmaxf(mx, __shfl_xor_sync(0xffffffffu, mx, off));
            float mnew = fmaxf(m_i[u], mx);
            float corr = __expf(m_i[u] - mnew);
            m_i[u] = mnew;
            float p0 = __expf(sv[0] - mnew);
            float p1 = __expf(sv[1] - mnew);
            float p2 = __expf(sv[2] - mnew);
            float p3 = __expf(sv[3] - mnew);
            *(float4*)&Ss[ty * 8 + u][tx * 4] = make_float4(p0, p1, p2, p3);
            float rsum = p0 + p1 + p2 + p3;
#pragma unroll
            for (int off = 8; off; off >>= 1)
                rsum += __shfl_xor_sync(0xffffffffu, rsum, off);
            l_i[u] = l_i[u] * corr + rsum;
#pragma unroll
            for (int c = 0; c < 4; c++) o[u][c] *= corr;
        }
        __syncthreads();

#pragma unroll 4
        for (int j = 0; j < 64; j++) {
            float4 vf = *(const float4*)&Vs[j][tx * 4];
#pragma unroll
            for (int u = 0; u < 8; u++) {
                float pj = Ss[ty * 8 + u][j];
                o[u][0] = fmaf(pj, vf.x, o[u][0]);
                o[u][1] = fmaf(pj, vf.y, o[u][1]);
                o[u][2] = fmaf(pj, vf.z, o[u][2]);
                o[u][3] = fmaf(pj, vf.w, o[u][3]);
            }
        }
    }

    // epilogue: normalize, split to bf16 hi/lo for proj GEMM
#pragma unroll
    for (int u = 0; u < 8; u++) {
        float inv = 1.0f / l_i[u];
        int nq = qt * 64 + ty * 8 + u;
        float r0 = o[u][0] * inv, r1 = o[u][1] * inv;
        float r2 = o[u][2] * inv, r3 = o[u][3] * inv;
        bf16 hh0 = __float2bfloat16_rn(r0), hh1 = __float2bfloat16_rn(r1);
        bf16 hh2 = __float2bfloat16_rn(r2), hh3 = __float2bfloat16_rn(r3);
        bf16 ll0 = __float2bfloat16_rn(r0 - __bfloat162float(hh0));
        bf16 ll1 = __float2bfloat16_rn(r1 - __bfloat162float(hh1));
        bf16 ll2 = __float2bfloat16_rn(r2 - __bfloat162float(hh2));
        bf16 ll3 = __float2bfloat16_rn(r3 - __bfloat162float(hh3));
        size_t off = ((size_t)(b * N_ + nq)) * C_ + h * 64 + tx * 4;
        __nv_bfloat162 ph01, ph23, pl01, pl23;
        ph01.x = hh0; ph01.y = hh1; ph23.x = hh2; ph23.y = hh3;
        pl01.x = ll0; pl01.y = ll1; pl23.x = ll2; pl23.y = ll3;
        *(__nv_bfloat162*)&g_atthi[off]     = ph01;
        *(__nv_bfloat162*)&g_atthi[off + 2] = ph23;
        *(__nv_bfloat162*)&g_attlo[off]     = pl01;
        *(__nv_bfloat162*)&g_attlo[off + 2] = pl23;
    }
}

// ---------------------------------------------------------------------------
extern "C" void kernel_launch(void* const* d_in, const int* in_sizes, int n_in,
                              void* d_out, int out_size) {
    const float*         x      = (const float*)d_in[0];
    const unsigned char* mask   = (const unsigned char*)d_in[1];
    const float*         w_qkv  = (const float*)d_in[2];
    const float*         w_proj = (const float*)d_in[3];
    const float*         b_proj = (const float*)d_in[4];
    const float*         qg     = (const float*)d_in[5];
    const float*         qb     = (const float*)d_in[6];
    const float*         kg     = (const float*)d_in[7];
    const float*         kb     = (const float*)d_in[8];
    float* out = (float*)d_out;

    // 0) split-bf16 conversions (sel: 0=x, 1=w_qkv, 2=w_proj)
    conv_kernel<<<4096, 256>>>(x, 0, (B_ * N_ * C_) / 4);
    conv_kernel<<<3072, 256>>>(w_qkv, 1, (3 * C_ * C_) / 4);
    conv_kernel<<<1024, 256>>>(w_proj, 2, (C_ * C_) / 4);

    // 1) QKV GEMM (mma.sync) + fused LN + scatter
    cudaFuncSetAttribute(qkv_mma_kernel, cudaFuncAttributeMaxDynamicSharedMemorySize, SMEM_GEMM);
    qkv_mma_kernel<<<dim3(24, 32), 256, SMEM_GEMM>>>(qg, qb, kg, kb);

    // 2) attention (fp32 SIMT), writes split-bf16 att
    const int smemF = 4 * 64 * SMP * (int)sizeof(float);
    cudaFuncSetAttribute(flash_kernel, cudaFuncAttributeMaxDynamicSharedMemorySize, smemF);
    flash_kernel<<<dim3(N_ / 64, H_, B_), 128, smemF>>>(mask);

    // 3) projection GEMM (mma.sync) + bias
    cudaFuncSetAttribute(proj_mma_kernel, cudaFuncAttributeMaxDynamicSharedMemorySize, SMEM_GEMM);
    proj_mma_kernel<<<dim3(8, 32), 256, SMEM_GEMM>>>(b_proj, out);
}

// round 5
// speedup vs baseline: 2.5502x; 1.7519x over previous
#include <cuda_runtime.h>
#include <cuda_bf16.h>
#include <cfloat>
#include <cstdint>

#define B_ 2
#define N_ 2048
#define C_ 1024
#define H_ 16
#define D_ 64

typedef __nv_bfloat16 bf16;

// ---------------------------------------------------------------------------
// Scratch (allocation-free rule: __device__ globals)
// ---------------------------------------------------------------------------
__device__ float g_v[B_ * H_ * N_ * D_];
__device__ bf16 g_qhi[B_ * H_ * N_ * D_], g_qlo[B_ * H_ * N_ * D_];
__device__ bf16 g_khi[B_ * H_ * N_ * D_], g_klo[B_ * H_ * N_ * D_];
__device__ bf16 g_vthi[B_ * H_ * D_ * N_], g_vtlo[B_ * H_ * D_ * N_];
__device__ bf16 g_xhi[B_ * N_ * C_], g_xlo[B_ * N_ * C_];
__device__ bf16 g_wqkvhi[3 * C_ * C_], g_wqkvlo[3 * C_ * C_];
__device__ bf16 g_wprojhi[C_ * C_], g_wprojlo[C_ * C_];
__device__ bf16 g_atthi[B_ * N_ * C_], g_attlo[B_ * N_ * C_];

// ---------------------------------------------------------------------------
// Family-agnostic PTX helpers
// ---------------------------------------------------------------------------
__device__ __forceinline__ uint32_t smem_u32(const void* p) {
    uint32_t a;
    asm("{ .reg .u64 t; cvta.to.shared.u64 t, %1; cvt.u32.u64 %0, t; }" : "=r"(a) : "l"(p));
    return a;
}
#define CP16(saddr, gptr) \
    asm volatile("cp.async.cg.shared.global [%0], [%1], 16;" ::"r"(saddr), "l"(gptr) : "memory")
#define CP_COMMIT() asm volatile("cp.async.commit_group;" ::: "memory")
#define CP_WAIT0()  asm volatile("cp.async.wait_group 0;" ::: "memory")

__device__ __forceinline__ void mma_bf16(float c[4], uint32_t a0, uint32_t a1, uint32_t a2,
                                         uint32_t a3, uint32_t b0, uint32_t b1) {
    asm volatile(
        "mma.sync.aligned.m16n8k16.row.col.f32.bf16.bf16.f32 "
        "{%0,%1,%2,%3},{%4,%5,%6,%7},{%8,%9},{%0,%1,%2,%3};"
        : "+f"(c[0]), "+f"(c[1]), "+f"(c[2]), "+f"(c[3])
        : "r"(a0), "r"(a1), "r"(a2), "r"(a3), "r"(b0), "r"(b1));
}

__device__ __forceinline__ uint32_t pack_bf16(bf16 lo, bf16 hi) {
    __nv_bfloat162 t; t.x = lo; t.y = hi;
    return *(uint32_t*)&t;
}
// split (x,y) -> packed hi-pair and lo-pair bf16x2
__device__ __forceinline__ void split2(float x, float y, uint32_t& hp, uint32_t& lp) {
    bf16 hx = __float2bfloat16_rn(x), hy = __float2bfloat16_rn(y);
    float lx = x - __bfloat162float(hx), ly = y - __bfloat162float(hy);
    hp = pack_bf16(hx, hy);
    lp = pack_bf16(__float2bfloat16_rn(lx), __float2bfloat16_rn(ly));
}

// ---------------------------------------------------------------------------
// 128x128x1024 split-bf16 (3-pass) mma.sync mainloop (unchanged from R4)
// ---------------------------------------------------------------------------
#define PITCH 40
#define CH (128 * PITCH)
#define CHB (CH * 2)
#define SMEM_GEMM (1024 + 8 * CHB)

__device__ __forceinline__ void gemm_ml(float acc[4][4][4],
                                        const bf16* __restrict__ Ahi,
                                        const bf16* __restrict__ Alo,
                                        const bf16* __restrict__ Bhi,
                                        const bf16* __restrict__ Blo,
                                        int m0, int n0, bf16* sa) {
    const int tid = threadIdx.x;
    const int wid = tid >> 5, lane = tid & 31;
    const int wm = wid & 1, wn = wid >> 1;
    const int r = lane >> 2, c4 = lane & 3;
    const int grow = tid >> 1, gcol = (tid & 1) * 16;

    const uint32_t sab = smem_u32(sa);
    const uint32_t so = (uint32_t)(grow * PITCH + gcol) * 2;

    const bf16* pAh = Ahi + (size_t)(m0 + grow) * C_ + gcol;
    const bf16* pAl = Alo + (size_t)(m0 + grow) * C_ + gcol;
    const bf16* pBh = Bhi + (size_t)(n0 + grow) * C_ + gcol;
    const bf16* pBl = Blo + (size_t)(n0 + grow) * C_ + gcol;

    {
        CP16(sab + 0 * CHB + so,      pAh);
        CP16(sab + 0 * CHB + so + 16, pAh + 8);
        CP16(sab + 2 * CHB + so,      pAl);
        CP16(sab + 2 * CHB + so + 16, pAl + 8);
        CP16(sab + 4 * CHB + so,      pBh);
        CP16(sab + 4 * CHB + so + 16, pBh + 8);
        CP16(sab + 6 * CHB + so,      pBl);
        CP16(sab + 6 * CHB + so + 16, pBl + 8);
        CP_COMMIT();
        CP_WAIT0();
    }
    __syncthreads();

    for (int c = 0; c < 32; c++) {
        if (c < 31) {
            const int k0 = (c + 1) * 32;
            const uint32_t nb = (uint32_t)((c + 1) & 1) * CHB;
            CP16(sab + 0 * CHB + nb + so,      pAh + k0);
            CP16(sab + 0 * CHB + nb + so + 16, pAh + k0 + 8);
            CP16(sab + 2 * CHB + nb + so,      pAl + k0);
            CP16(sab + 2 * CHB + nb + so + 16, pAl + k0 + 8);
            CP16(sab + 4 * CHB + nb + so,      pBh + k0);
            CP16(sab + 4 * CHB + nb + so + 16, pBh + k0 + 8);
            CP16(sab + 6 * CHB + nb + so,      pBl + k0);
            CP16(sab + 6 * CHB + nb + so + 16, pBl + k0 + 8);
            CP_COMMIT();
        }
        const int bo = (c & 1) * CH;
        const bf16* ah = sa + bo;
        const bf16* al = sa + 2 * CH + bo;
        const bf16* bh = sa + 4 * CH + bo;
        const bf16* bl = sa + 6 * CH + bo;
#pragma unroll
        for (int kf = 0; kf < 2; kf++) {
            const int kb = kf * 16 + c4 * 2;
            uint32_t afh[4][4], afl[4][4];
#pragma unroll
            for (int mf = 0; mf < 4; mf++) {
                const int row = wm * 64 + mf * 16 + r;
                afh[mf][0] = *(const uint32_t*)(ah + row * PITCH + kb);
                afh[mf][1] = *(const uint32_t*)(ah + (row + 8) * PITCH + kb);
                afh[mf][2] = *(const uint32_t*)(ah + row * PITCH + kb + 8);
                afh[mf][3] = *(const uint32_t*)(ah + (row + 8) * PITCH + kb + 8);
                afl[mf][0] = *(const uint32_t*)(al + row * PITCH + kb);
                afl[mf][1] = *(const uint32_t*)(al + (row + 8) * PITCH + kb);
                afl[mf][2] = *(const uint32_t*)(al + row * PITCH + kb + 8);
                afl[mf][3] = *(const uint32_t*)(al + (row + 8) * PITCH + kb + 8);
            }
            uint32_t bfh[4][2], bfl[4][2];
#pragma unroll
            for (int nf = 0; nf < 4; nf++) {
                const int nn = wn * 32 + nf * 8 + r;
                bfh[nf][0] = *(const uint32_t*)(bh + nn * PITCH + kb);
                bfh[nf][1] = *(const uint32_t*)(bh + nn * PITCH + kb + 8);
                bfl[nf][0] = *(const uint32_t*)(bl + nn * PITCH + kb);
                bfl[nf][1] = *(const uint32_t*)(bl + nn * PITCH + kb + 8);
            }
#pragma unroll
            for (int mf = 0; mf < 4; mf++)
#pragma unroll
                for (int nf = 0; nf < 4; nf++) {
                    mma_bf16(acc[mf][nf], afh[mf][0], afh[mf][1], afh[mf][2], afh[mf][3],
                             bfh[nf][0], bfh[nf][1]);
                    mma_bf16(acc[mf][nf], afh[mf][0], afh[mf][1], afh[mf][2], afh[mf][3],
                             bfl[nf][0], bfl[nf][1]);
                    mma_bf16(acc[mf][nf], afl[mf][0], afl[mf][1], afl[mf][2], afl[mf][3],
                             bfh[nf][0], bfh[nf][1]);
                }
        }
        if (c < 31) CP_WAIT0();
        __syncthreads();
    }
}

// ---------------------------------------------------------------------------
// fp32 -> (hi, lo) bf16 split
// ---------------------------------------------------------------------------
__global__ __launch_bounds__(256) void conv_kernel(const float* __restrict__ src,
                                                   int sel, int n4) {
    bf16* hi = (sel == 0) ? g_xhi : (sel == 1) ? g_wqkvhi : g_wprojhi;
    bf16* lo = (sel == 0) ? g_xlo : (sel == 1) ? g_wqkvlo : g_wprojlo;
    int i = blockIdx.x * 256 + threadIdx.x;
    if (i >= n4) return;
    float4 v = ((const float4*)src)[i];
    float a[4] = {v.x, v.y, v.z, v.w};
    uint32_t hp[2], lp[2];
    split2(a[0], a[1], hp[0], lp[0]);
    split2(a[2], a[3], hp[1], lp[1]);
    *(uint32_t*)(hi + 4 * (size_t)i)     = hp[0];
    *(uint32_t*)(hi + 4 * (size_t)i + 2) = hp[1];
    *(uint32_t*)(lo + 4 * (size_t)i)     = lp[0];
    *(uint32_t*)(lo + 4 * (size_t)i + 2) = lp[1];
}

// ---------------------------------------------------------------------------
// QKV GEMM + fused per-head LayerNorm; Q,K out as bf16 hi/lo; V out fp32.
// ---------------------------------------------------------------------------
#define DPITCH 132

__global__ __launch_bounds__(256) void qkv_mma_kernel(const float* __restrict__ qg,
                                                      const float* __restrict__ qb,
                                                      const float* __restrict__ kg,
                                                      const float* __restrict__ kb) {
    extern __shared__ char smc[];
    float* sgam = (float*)smc;
    float* sbet = (float*)(smc + 256);
    bf16* sa = (bf16*)(smc + 1024);

    const int n0 = blockIdx.x * 128, m0 = blockIdx.y * 128;
    const int s = n0 >> 10;
    if (threadIdx.x < 64 && s < 2) {
        const float* gg = (s == 0) ? qg : kg;
        const float* bb = (s == 0) ? qb : kb;
        sgam[threadIdx.x] = gg[threadIdx.x];
        sbet[threadIdx.x] = bb[threadIdx.x];
    }

    float acc[4][4][4];
#pragma unroll
    for (int a = 0; a < 4; a++)
#pragma unroll
        for (int b = 0; b < 4; b++)
#pragma unroll
            for (int cc = 0; cc < 4; cc++) acc[a][b][cc] = 0.f;

    gemm_ml(acc, g_xhi, g_xlo, g_wqkvhi, g_wqkvlo, m0, n0, sa);

    float* Dst = (float*)(smc + 1024);
    const int wid = threadIdx.x >> 5, lane = threadIdx.x & 31;
    const int wm = wid & 1, wn = wid >> 1;
    const int r = lane >> 2, c4 = lane & 3;
#pragma unroll
    for (int mf = 0; mf < 4; mf++)
#pragma unroll
        for (int nf = 0; nf < 4; nf++) {
            const int m = wm * 64 + mf * 16 + r;
            const int n = wn * 32 + nf * 8 + c4 * 2;
            *(float2*)&Dst[m * DPITCH + n]       = make_float2(acc[mf][nf][0], acc[mf][nf][1]);
            *(float2*)&Dst[(m + 8) * DPITCH + n] = make_float2(acc[mf][nf][2], acc[mf][nf][3]);
        }
    __syncthreads();

    const int m = threadIdx.x >> 1, hc = threadIdx.x & 1;
    const float* rowp = Dst + m * DPITCH + hc * 64;
    float f[64];
#pragma unroll
    for (int i = 0; i < 64; i++) f[i] = rowp[i];
    const int bidx = m0 >> 11, nq = (m0 & 2047) + m;
    const int h = ((n0 & 1023) >> 6) + hc;
    const size_t base = (((size_t)(bidx * H_ + h)) * N_ + nq) * D_;
    if (s < 2) {
        float sum = 0.f;
#pragma unroll
        for (int i = 0; i < 64; i++) sum += f[i];
        float mu = sum * (1.0f / 64.0f);
        float vs = 0.f;
#pragma unroll
        for (int i = 0; i < 64; i++) { float d = f[i] - mu; vs += d * d; }
        float rs = rsqrtf(vs * (1.0f / 64.0f) + 1e-5f);
#pragma unroll
        for (int i = 0; i < 64; i++) f[i] = (f[i] - mu) * rs * sgam[i] + sbet[i];
        bf16* dh = (s == 0) ? g_qhi : g_khi;
        bf16* dl = (s == 0) ? g_qlo : g_klo;
#pragma unroll
        for (int i = 0; i < 64; i += 2) {
            uint32_t hp, lp;
            split2(f[i], f[i + 1], hp, lp);
            *(uint32_t*)(dh + base + i) = hp;
            *(uint32_t*)(dl + base + i) = lp;
        }
    } else {
#pragma unroll
        for (int i = 0; i < 64; i += 4)
            *(float4*)&g_v[base + i] = make_float4(f[i], f[i + 1], f[i + 2], f[i + 3]);
    }
}

// ---------------------------------------------------------------------------
// V transpose + split:  g_v[b,h,key,d] -> g_vthi/lo[b,h,d,key]
// grid (N_/64, B_*H_), 256 threads
// ---------------------------------------------------------------------------
__global__ __launch_bounds__(256) void vt_kernel() {
    __shared__ float tile[64][65];
    const int kt = blockIdx.x, bh = blockIdx.y;
    const int tid = threadIdx.x;
    const float* src = g_v + (size_t)bh * N_ * D_ + (size_t)(kt * 64) * D_;
#pragma unroll
    for (int j = 0; j < 4; j++) {
        int id = tid + j * 256;
        int row = id >> 4, c4i = (id & 15) * 4;
        float4 v = *(const float4*)(src + row * D_ + c4i);
        tile[row][c4i] = v.x; tile[row][c4i + 1] = v.y;
        tile[row][c4i + 2] = v.z; tile[row][c4i + 3] = v.w;
    }
    __syncthreads();
    const int d = tid >> 2, kg = (tid & 3) * 16;
    bf16* dh = g_vthi + (size_t)bh * D_ * N_ + (size_t)d * N_ + kt * 64 + kg;
    bf16* dl = g_vtlo + (size_t)bh * D_ * N_ + (size_t)d * N_ + kt * 64 + kg;
#pragma unroll
    for (int i = 0; i < 16; i += 2) {
        uint32_t hp, lp;
        split2(tile[kg + i][d], tile[kg + i + 1][d], hp, lp);
        *(uint32_t*)(dh + i) = hp;
        *(uint32_t*)(dl + i) = lp;
    }
}

// ---------------------------------------------------------------------------
// Flash attention on mma.sync (split-bf16, 3-pass QK^T and PV).
// CTA: 128 q-rows, 8 warps (16 rows each), Bc = 64 keys/iter.
// ---------------------------------------------------------------------------
#define FP 72                      // smem pitch in halves
#define KTILE (64 * FP)            // halves per tile array
#define SMEM_FLASH (8 * KTILE * 2) // 2 bufs x 4 arrays x 9216B = 73728

__global__ __launch_bounds__(256) void flash_mma_kernel(const unsigned char* __restrict__ mask) {
    extern __shared__ char smc[];
    bf16* sh = (bf16*)smc;
    const uint32_t shb = smem_u32(sh);

    const int qt = blockIdx.x, h = blockIdx.y, b = blockIdx.z;
    const int tid = threadIdx.x, wid = tid >> 5, lane = tid & 31;
    const int r = lane >> 2, c4 = lane & 3;
    const int wrow = wid * 16;
    const size_t qkoff = ((size_t)(b * H_ + h)) * N_ * D_;
    const size_t vtoff = ((size_t)(b * H_ + h)) * D_ * N_;

    // ---- stage Q tile (hi at 0, lo at KTILE*2 halves) and read fragments ----
    {
        const bf16* qh = g_qhi + qkoff + (size_t)(qt * 128) * D_;
        const bf16* ql = g_qlo + qkoff + (size_t)(qt * 128) * D_;
#pragma unroll
        for (int j = 0; j < 4; j++) {
            int id = tid + j * 256;
            int row = id >> 3, c8 = (id & 7) * 8;
            CP16(shb + (row * FP + c8) * 2, qh + row * D_ + c8);
            CP16(shb + (2 * KTILE + row * FP + c8) * 2, ql + row * D_ + c8);
        }
        CP_COMMIT(); CP_WAIT0();
    }
    __syncthreads();

    uint32_t aQh[4][4], aQl[4][4];
#pragma unroll
    for (int kc = 0; kc < 4; kc++) {
        const int ba = (wrow + r) * FP + kc * 16 + c4 * 2;
        aQh[kc][0] = *(const uint32_t*)(sh + ba);
        aQh[kc][1] = *(const uint32_t*)(sh + ba + 8 * FP);
        aQh[kc][2] = *(const uint32_t*)(sh + ba + 8);
        aQh[kc][3] = *(const uint32_t*)(sh + ba + 8 * FP + 8);
        aQl[kc][0] = *(const uint32_t*)(sh + 2 * KTILE + ba);
        aQl[kc][1] = *(const uint32_t*)(sh + 2 * KTILE + ba + 8 * FP);
        aQl[kc][2] = *(const uint32_t*)(sh + 2 * KTILE + ba + 8);
        aQl[kc][3] = *(const uint32_t*)(sh + 2 * KTILE + ba + 8 * FP + 8);
    }
    __syncthreads();

    float of[8][4];
#pragma unroll
    for (int nb = 0; nb < 8; nb++)
#pragma unroll
        for (int k = 0; k < 4; k++) of[nb][k] = 0.f;
    float mI0 = -FLT_MAX, mI1 = -FLT_MAX, l0 = 0.f, l1 = 0.f;

    // tile loader: arrays 0=Kh 1=Kl 2=Vth 3=Vtl
    auto issue_tile = [&](int kt2, int buf) {
        const uint32_t bo = (uint32_t)buf * 4 * KTILE * 2;
        const bf16* kh = g_khi + qkoff + (size_t)(kt2 * 64) * D_;
        const bf16* kl = g_klo + qkoff + (size_t)(kt2 * 64) * D_;
        const bf16* vh = g_vthi + vtoff + kt2 * 64;
        const bf16* vl = g_vtlo + vtoff + kt2 * 64;
#pragma unroll
        for (int j = 0; j < 2; j++) {
            int id = tid + j * 256;
            int row = id >> 3, c8 = (id & 7) * 8;
            uint32_t sd = bo + (row * FP + c8) * 2;
            CP16(shb + sd, kh + row * D_ + c8);
            CP16(shb + sd + KTILE * 2, kl + row * D_ + c8);
            CP16(shb + sd + 2 * KTILE * 2, vh + (size_t)row * N_ + c8);
            CP16(shb + sd + 3 * KTILE * 2, vl + (size_t)row * N_ + c8);
        }
        CP_COMMIT();
    };

    issue_tile(0, 0);
    CP_WAIT0();
    __syncthreads();

    const unsigned char* mb0 = mask + ((size_t)b * N_ + qt * 128 + wrow + r) * N_;
    const float scale = 0.125f;

    for (int kt2 = 0; kt2 < N_ / 64; kt2++) {
        if (kt2 < N_ / 64 - 1) issue_tile(kt2 + 1, (kt2 + 1) & 1);

        const bf16* sKh = sh + ((kt2 & 1) * 4 + 0) * KTILE;
        const bf16* sKl = sh + ((kt2 & 1) * 4 + 1) * KTILE;
        const bf16* sVh = sh + ((kt2 & 1) * 4 + 2) * KTILE;
        const bf16* sVl = sh + ((kt2 & 1) * 4 + 3) * KTILE;

        // ---- S = Q K^T (3-pass) ----
        float sf[8][4];
#pragma unroll
        for (int nb = 0; nb < 8; nb++) {
            sf[nb][0] = sf[nb][1] = sf[nb][2] = sf[nb][3] = 0.f;
            const int kb = (nb * 8 + r) * FP + c4 * 2;
            uint32_t bh0[4], bh1[4], bl0[4], bl1[4];
#pragma unroll
            for (int kc = 0; kc < 4; kc++) {
                bh0[kc] = *(const uint32_t*)(sKh + kb + kc * 16);
                bh1[kc] = *(const uint32_t*)(sKh + kb + kc * 16 + 8);
                bl0[kc] = *(const uint32_t*)(sKl + kb + kc * 16);
                bl1[kc] = *(const uint32_t*)(sKl + kb + kc * 16 + 8);
            }
#pragma unroll
            for (int kc = 0; kc < 4; kc++) {
                mma_bf16(sf[nb], aQh[kc][0], aQh[kc][1], aQh[kc][2], aQh[kc][3], bh0[kc], bh1[kc]);
                mma_bf16(sf[nb], aQh[kc][0], aQh[kc][1], aQh[kc][2], aQh[kc][3], bl0[kc], bl1[kc]);
                mma_bf16(sf[nb], aQl[kc][0], aQl[kc][1], aQl[kc][2], aQl[kc][3], bh0[kc], bh1[kc]);
            }
        }

        // ---- scale + mask ----
        const unsigned char* mr0 = mb0 + kt2 * 64 + c4 * 2;
#pragma unroll
        for (int nb = 0; nb < 8; nb++) {
            uchar2 k0 = *(const uchar2*)(mr0 + nb * 8);
            uchar2 k8 = *(const uchar2*)(mr0 + 8 * N_ + nb * 8);
            sf[nb][0] = k0.x ? -FLT_MAX : sf[nb][0] * scale;
            sf[nb][1] = k0.y ? -FLT_MAX : sf[nb][1] * scale;
            sf[nb][2] = k8.x ? -FLT_MAX : sf[nb][2] * scale;
            sf[nb][3] = k8.y ? -FLT_MAX : sf[nb][3] * scale;
        }

        // ---- online softmax ----
        float mx0 = -FLT_MAX, mx1 = -FLT_MAX;
#pragma unroll
        for (int nb = 0; nb < 8; nb++) {
            mx0 = fmaxf(mx0, fmaxf(sf[nb][0], sf[nb][1]));
            mx1 = fmaxf(mx1, fmaxf(sf[nb][2], sf[nb][3]));
        }
        mx0 = fmaxf(mx0, __shfl_xor_sync(0xffffffffu, mx0, 1));
        mx0 = fmaxf(mx0, __shfl_xor_sync(0xffffffffu, mx0, 2));
        mx1 = fmaxf(mx1, __shfl_xor_sync(0xffffffffu, mx1, 1));
        mx1 = fmaxf(mx1, __shfl_xor_sync(0xffffffffu, mx1, 2));
        const float mn0 = fmaxf(mI0, mx0), mn1 = fmaxf(mI1, mx1);
        const float cor0 = __expf(mI0 - mn0), cor1 = __expf(mI1 - mn1);
        mI0 = mn0; mI1 = mn1;
        float rs0 = 0.f, rs1 = 0.f;
#pragma unroll
        for (int nb = 0; nb < 8; nb++) {
            sf[nb][0] = __expf(sf[nb][0] - mn0);
            sf[nb][1] = __expf(sf[nb][1] - mn0);
            sf[nb][2] = __expf(sf[nb][2] - mn1);
            sf[nb][3] = __expf(sf[nb][3] - mn1);
            rs0 += sf[nb][0] + sf[nb][1];
            rs1 += sf[nb][2] + sf[nb][3];
        }
        rs0 += __shfl_xor_sync(0xffffffffu, rs0, 1);
        rs0 += __shfl_xor_sync(0xffffffffu, rs0, 2);
        rs1 += __shfl_xor_sync(0xffffffffu, rs1, 1);
        rs1 += __shfl_xor_sync(0xffffffffu, rs1, 2);
        l0 = l0 * cor0 + rs0;
        l1 = l1 * cor1 + rs1;
#pragma unroll
        for (int nb = 0; nb < 8; nb++) {
            of[nb][0] *= cor0; of[nb][1] *= cor0;
            of[nb][2] *= cor1; of[nb][3] *= cor1;
        }

        // ---- O += P V (3-pass) ----
#pragma unroll
        for (int kc = 0; kc < 4; kc++) {
            uint32_t ah[4], al[4];
            split2(sf[2 * kc][0], sf[2 * kc][1], ah[0], al[0]);
            split2(sf[2 * kc][2], sf[2 * kc][3], ah[1], al[1]);
            split2(sf[2 * kc + 1][0], sf[2 * kc + 1][1], ah[2], al[2]);
            split2(sf[2 * kc + 1][2], sf[2 * kc + 1][3], ah[3], al[3]);
#pragma unroll
            for (int nb = 0; nb < 8; nb++) {
                const int vb = (nb * 8 + r) * FP + kc * 16 + c4 * 2;
                uint32_t vh0 = *(const uint32_t*)(sVh + vb);
                uint32_t vh1 = *(const uint32_t*)(sVh + vb + 8);
                uint32_t vl0 = *(const uint32_t*)(sVl + vb);
                uint32_t vl1 = *(const uint32_t*)(sVl + vb + 8);
                mma_bf16(of[nb], ah[0], ah[1], ah[2], ah[3], vh0, vh1);
                mma_bf16(of[nb], ah[0], ah[1], ah[2], ah[3], vl0, vl1);
                mma_bf16(of[nb], al[0], al[1], al[2], al[3], vh0, vh1);
            }
        }

        if (kt2 < N_ / 64 - 1) CP_WAIT0();
        __syncthreads();
    }

    // ---- epilogue: normalize, write split bf16 att [B,N,C] ----
    const float inv0 = 1.0f / l0, inv1 = 1.0f / l1;
    const int row0 = qt * 128 + wrow + r;
    const size_t ob0 = ((size_t)b * N_ + row0) * C_ + h * 64 + c4 * 2;
    const size_t ob1 = ob0 + 8 * (size_t)C_;
#pragma unroll
    for (int nb = 0; nb < 8; nb++) {
        uint32_t hp, lp;
        split2(of[nb][0] * inv0, of[nb][1] * inv0, hp, lp);
        *(uint32_t*)(g_atthi + ob0 + nb * 8) = hp;
        *(uint32_t*)(g_attlo + ob0 + nb * 8) = lp;
        split2(of[nb][2] * inv1, of[nb][3] * inv1, hp, lp);
        *(uint32_t*)(g_atthi + ob1 + nb * 8) = hp;
        *(uint32_t*)(g_attlo + ob1 + nb * 8) = lp;
    }
}

// ---------------------------------------------------------------------------
// Projection GEMM + bias
// ---------------------------------------------------------------------------
__global__ __launch_bounds__(256) void proj_mma_kernel(const float* __restrict__ bias,
                                                       float* __restrict__ out) {
    extern __shared__ char smc[];
    float* sbias = (float*)smc;
    bf16* sa = (bf16*)(smc + 1024);
    const int n0 = blockIdx.x * 128, m0 = blockIdx.y * 128;
    if (threadIdx.x < 128) sbias[threadIdx.x] = bias[n0 + threadIdx.x];

    float acc[4][4][4];
#pragma unroll
    for (int a = 0; a < 4; a++)
#pragma unroll
        for (int b = 0; b < 4; b++)
#pragma unroll
            for (int cc = 0; cc < 4; cc++) acc[a][b][cc] = 0.f;

    gemm_ml(acc, g_atthi, g_attlo, g_wprojhi, g_wprojlo, m0, n0, sa);

    const int wid = threadIdx.x >> 5, lane = threadIdx.x & 31;
    const int wm = wid & 1, wn = wid >> 1;
    const int r = lane >> 2, c4 = lane & 3;
#pragma unroll
    for (int mf = 0; mf < 4; mf++)
#pragma unroll
        for (int nf = 0; nf < 4; nf++) {
            const int m = wm * 64 + mf * 16 + r;
            const int n = wn * 32 + nf * 8 + c4 * 2;
            const float b0 = sbias[n], b1 = sbias[n + 1];
            *(float2*)&out[(size_t)(m0 + m) * C_ + n0 + n] =
                make_float2(acc[mf][nf][0] + b0, acc[mf][nf][1] + b1);
            *(float2*)&out[(size_t)(m0 + m + 8) * C_ + n0 + n] =
                make_float2(acc[mf][nf][2] + b0, acc[mf][nf][3] + b1);
        }
}

// ---------------------------------------------------------------------------
extern "C" void kernel_launch(void* const* d_in, const int* in_sizes, int n_in,
                              void* d_out, int out_size) {
    const float*         x      = (const float*)d_in[0];
    const unsigned char* mask   = (const unsigned char*)d_in[1];
    const float*         w_qkv  = (const float*)d_in[2];
    const float*         w_proj = (const float*)d_in[3];
    const float*         b_proj = (const float*)d_in[4];
    const float*         qg     = (const float*)d_in[5];
    const float*         qb     = (const float*)d_in[6];
    const float*         kg     = (const float*)d_in[7];
    const float*         kb     = (const float*)d_in[8];
    float* out = (float*)d_out;

    conv_kernel<<<4096, 256>>>(x, 0, (B_ * N_ * C_) / 4);
    conv_kernel<<<3072, 256>>>(w_qkv, 1, (3 * C_ * C_) / 4);
    conv_kernel<<<1024, 256>>>(w_proj, 2, (C_ * C_) / 4);

    cudaFuncSetAttribute(qkv_mma_kernel, cudaFuncAttributeMaxDynamicSharedMemorySize, SMEM_GEMM);
    qkv_mma_kernel<<<dim3(24, 32), 256, SMEM_GEMM>>>(qg, qb, kg, kb);

    vt_kernel<<<dim3(N_ / 64, B_ * H_), 256>>>();

    cudaFuncSetAttribute(flash_mma_kernel, cudaFuncAttributeMaxDynamicSharedMemorySize, SMEM_FLASH);
    flash_mma_kernel<<<dim3(N_ / 128, H_, B_), 256, SMEM_FLASH>>>(mask);

    cudaFuncSetAttribute(proj_mma_kernel, cudaFuncAttributeMaxDynamicSharedMemorySize, SMEM_GEMM);
    proj_mma_kernel<<<dim3(8, 32), 256, SMEM_GEMM>>>(b_proj, out);
}